// round 3
// baseline (speedup 1.0000x reference)
#include <cuda_runtime.h>
#include <cstdint>

#define H 2048
#define B 16
#define S 256
#define V 32000

// 16MB transposed alpha: g_alphaT[k*H + r] = alpha[r*H + k]
__device__ float g_alphaT[(size_t)H * H];
__device__ float g_gamma_exp[H];

struct __align__(16) ULL2 { unsigned long long x, y; };

__device__ __forceinline__ unsigned long long pk2(float v) {
    unsigned long long r;
    asm("mov.b64 %0, {%1, %1};" : "=l"(r) : "f"(v));
    return r;
}
__device__ __forceinline__ unsigned long long fma2(unsigned long long a, unsigned long long b,
                                                   unsigned long long c) {
    unsigned long long d;
    asm("fma.rn.f32x2 %0, %1, %2, %3;" : "=l"(d) : "l"(a), "l"(b), "l"(c));
    return d;
}
__device__ __forceinline__ void upk(unsigned long long v, float& lo, float& hi) {
    asm("mov.b64 {%0, %1}, %2;" : "=f"(lo), "=f"(hi) : "l"(v));
}

// ---------------------------------------------------------------------------
// alpha -> alphaT transpose (one-time per launch)
// ---------------------------------------------------------------------------
__global__ void transpose_kernel(const float* __restrict__ a) {
    __shared__ float tile[32][33];
    int bx = blockIdx.x * 32;  // k tile
    int by = blockIdx.y * 32;  // r tile
    int tx = threadIdx.x, ty = threadIdx.y;
    #pragma unroll
    for (int i = 0; i < 32; i += 8)
        tile[ty + i][tx] = a[(size_t)(by + ty + i) * H + (bx + tx)];
    __syncthreads();
    #pragma unroll
    for (int i = 0; i < 32; i += 8)
        g_alphaT[(size_t)(bx + ty + i) * H + (by + tx)] = tile[tx][ty + i];
}

// ---------------------------------------------------------------------------
// gamma softmax (one block)
// ---------------------------------------------------------------------------
__global__ void gamma_kernel(const float* __restrict__ gamma) {
    __shared__ float red[256];
    __shared__ float s_max, s_sum;
    int tid = threadIdx.x;
    float mx = -3.4e38f;
    for (int i = tid; i < H; i += 256) mx = fmaxf(mx, gamma[i]);
    red[tid] = mx;
    __syncthreads();
    for (int o = 128; o > 0; o >>= 1) {
        if (tid < o) red[tid] = fmaxf(red[tid], red[tid + o]);
        __syncthreads();
    }
    if (tid == 0) s_max = red[0];
    __syncthreads();
    float m = s_max;
    float sm = 0.f;
    for (int i = tid; i < H; i += 256) sm += __expf(gamma[i] - m);
    __syncthreads();
    red[tid] = sm;
    __syncthreads();
    for (int o = 128; o > 0; o >>= 1) {
        if (tid < o) red[tid] += red[tid + o];
        __syncthreads();
    }
    if (tid == 0) s_sum = red[0];
    __syncthreads();
    float inv = 1.0f / s_sum;
    for (int i = tid; i < H; i += 256) g_gamma_exp[i] = __expf(gamma[i] - m) * inv;
}

// ---------------------------------------------------------------------------
// t = 0: ys[0][h][b] = beta[h, ids[b, S-1]]  (masked)
// ---------------------------------------------------------------------------
__global__ void init_kernel(const int* __restrict__ ids, const float* __restrict__ beta,
                            float* __restrict__ ys) {
    int idx = blockIdx.x * blockDim.x + threadIdx.x;  // 0..H*B
    int h = idx >> 4, b = idx & 15;
    int id = ids[b * S + (S - 1)];
    float v = (id < 0) ? 0.f : __ldg(&beta[(size_t)h * V + id]);
    ys[idx] = v;
}

// ---------------------------------------------------------------------------
// one recurrence step: ys[t] = log(alpha @ exp(ys[t-1]-m)) + m + ip_rev[t]
// 128 blocks x 16 rows, 256 threads, 128KB dynamic smem
// ---------------------------------------------------------------------------
__global__ __launch_bounds__(256) void step_kernel(int t, const int* __restrict__ ids,
                                                   const float* __restrict__ beta,
                                                   float* __restrict__ ys) {
    extern __shared__ float s[];  // H*B floats (y, then exp(y-m), then partials)
    __shared__ float redmax[16][16];
    __shared__ float mvals[16];

    const int tid = threadIdx.x;
    const float* __restrict__ yp = ys + (size_t)(t - 1) * H * B;
    float* __restrict__ yo = ys + (size_t)t * H * B;
    const int r0 = blockIdx.x * 16;

    // early scattered gather of ip (beta column) for this thread's output (orow, ob)
    const int ob = tid & 15, orow = tid >> 4;
    const int id = ids[ob * S + (S - 1 - t)];
    const float ipv = (id < 0) ? 0.f : __ldg(&beta[(size_t)(r0 + orow) * V + id]);

    // phase 1: load y_prev into smem (L2-fresh via .cg)
    {
        const float4* yp4 = reinterpret_cast<const float4*>(yp);
        float4* s4 = reinterpret_cast<float4*>(s);
        #pragma unroll
        for (int i = 0; i < (H * B / 4) / 256; i++)
            s4[i * 256 + tid] = __ldcg(&yp4[i * 256 + tid]);
    }
    __syncthreads();

    // phase 2: per-batch max over H
    {
        int b = tid & 15, seg = tid >> 4;
        float mx = -3.4e38f;
        const float* p = s + seg * 128 * B + b;
        #pragma unroll 8
        for (int h = 0; h < 128; h++) mx = fmaxf(mx, p[h * B]);
        redmax[seg][b] = mx;
    }
    __syncthreads();
    if (tid < 16) {
        float mx = redmax[0][tid];
        #pragma unroll
        for (int c = 1; c < 16; c++) mx = fmaxf(mx, redmax[c][tid]);
        mvals[tid] = mx;
    }
    __syncthreads();

    // phase 3: exp in place
    {
        #pragma unroll
        for (int i = 0; i < (H * B) / 256; i++) {
            int j = i * 256 + tid;
            s[j] = __expf(s[j] - mvals[j & 15]);
        }
    }
    __syncthreads();

    // phase 4: dot products with f32x2 (row-pairs packed via transposed alpha)
    // thread: bg = tid&7 (b0 = 2*bg), rg = (tid>>3)&1 (8 rows), kseg = tid>>4 (128 k each)
    const int bg = tid & 7, rg = (tid >> 3) & 1, kseg = tid >> 4;
    const int b0 = bg * 2;
    const float* atp = g_alphaT + (size_t)(kseg * 128) * H + r0 + rg * 8;
    const float* sp = s + (kseg * 128) * B + b0;

    unsigned long long acc[4][2];
    #pragma unroll
    for (int i = 0; i < 4; i++) { acc[i][0] = 0ull; acc[i][1] = 0ull; }

    #pragma unroll 4
    for (int k = 0; k < 128; k++) {
        unsigned long long sv = *reinterpret_cast<const unsigned long long*>(sp);
        float sl, sh;
        upk(sv, sl, sh);
        unsigned long long d0 = pk2(sl);
        unsigned long long d1 = pk2(sh);
        ULL2 a01 = *reinterpret_cast<const ULL2*>(atp);
        ULL2 a23 = *reinterpret_cast<const ULL2*>(atp + 4);
        acc[0][0] = fma2(a01.x, d0, acc[0][0]);
        acc[0][1] = fma2(a01.x, d1, acc[0][1]);
        acc[1][0] = fma2(a01.y, d0, acc[1][0]);
        acc[1][1] = fma2(a01.y, d1, acc[1][1]);
        acc[2][0] = fma2(a23.x, d0, acc[2][0]);
        acc[2][1] = fma2(a23.x, d1, acc[2][1]);
        acc[3][0] = fma2(a23.y, d0, acc[3][0]);
        acc[3][1] = fma2(a23.y, d1, acc[3][1]);
        sp += B;
        atp += H;
    }
    __syncthreads();  // done reading s; reuse as partial buffer

    // partials: part[(row_local*16 + b)*16 + kseg]
    float* part = s;
    #pragma unroll
    for (int i = 0; i < 4; i++) {
        float lo, hi;
        upk(acc[i][0], lo, hi);
        part[(((rg * 8 + 2 * i) * 16) + b0) * 16 + kseg] = lo;
        part[(((rg * 8 + 2 * i + 1) * 16) + b0) * 16 + kseg] = hi;
        upk(acc[i][1], lo, hi);
        part[(((rg * 8 + 2 * i) * 16) + b0 + 1) * 16 + kseg] = lo;
        part[(((rg * 8 + 2 * i + 1) * 16) + b0 + 1) * 16 + kseg] = hi;
    }
    __syncthreads();

    // reduce 16 k-segments, add log + max + ip, store
    {
        float sum = 0.f;
        const float* pp = part + tid * 16;
        #pragma unroll
        for (int c = 0; c < 16; c++) sum += pp[c];
        yo[(size_t)(r0 + orow) * B + ob] = __logf(sum) + mvals[ob] + ipv;
    }
}

// ---------------------------------------------------------------------------
// final[b] = log(gamma_exp . exp(y_last[:,b] - m_b)) + m_b
// ---------------------------------------------------------------------------
__global__ void final_kernel(float* __restrict__ out) {
    __shared__ float redm[16][16];
    __shared__ float reds[16][16];
    __shared__ float mv[16];
    int tid = threadIdx.x;
    int b = tid & 15, seg = tid >> 4;
    const float* yl = out + (size_t)(S - 1) * H * B;
    float mx = -3.4e38f;
    for (int h = seg; h < H; h += 16) mx = fmaxf(mx, yl[h * B + b]);
    redm[seg][b] = mx;
    __syncthreads();
    if (tid < 16) {
        float m2 = redm[0][tid];
        #pragma unroll
        for (int c = 1; c < 16; c++) m2 = fmaxf(m2, redm[c][tid]);
        mv[tid] = m2;
    }
    __syncthreads();
    float m = mv[b];
    float sm = 0.f;
    for (int h = seg; h < H; h += 16) sm += g_gamma_exp[h] * __expf(yl[h * B + b] - m);
    reds[seg][b] = sm;
    __syncthreads();
    if (tid < 16) {
        float tot = 0.f;
        #pragma unroll
        for (int c = 0; c < 16; c++) tot += reds[c][tid];
        out[(size_t)S * H * B + tid] = __logf(tot) + mv[tid];
    }
}

// ---------------------------------------------------------------------------
extern "C" void kernel_launch(void* const* d_in, const int* in_sizes, int n_in,
                              void* d_out, int out_size) {
    const int* ids = (const int*)d_in[0];        // (B, S) int32
    const float* alpha = (const float*)d_in[1];  // (H, H)
    const float* beta = (const float*)d_in[2];   // (H, V)
    const float* gamma = (const float*)d_in[3];  // (H,)
    float* out = (float*)d_out;                  // ys (S,H,B) then final (B,)

    cudaFuncSetAttribute(step_kernel, cudaFuncAttributeMaxDynamicSharedMemorySize,
                         H * B * (int)sizeof(float));

    dim3 tg(H / 32, H / 32), tb(32, 8);
    transpose_kernel<<<tg, tb>>>(alpha);
    gamma_kernel<<<1, 256>>>(gamma);
    init_kernel<<<H * B / 256, 256>>>(ids, beta, out);
    for (int t = 1; t < S; t++)
        step_kernel<<<H / 16, 256, H * B * sizeof(float)>>>(t, ids, beta, out);
    final_kernel<<<1, 256>>>(out);
}

// round 4
// speedup vs baseline: 3.3885x; 3.3885x over previous
#include <cuda_runtime.h>
#include <cstdint>

#define H 2048
#define B 16
#define S 256
#define V 32000
#define NBLK 128
#define NTHR 512

typedef unsigned long long ull;

__device__ float g_gamma_exp[H];
__device__ float g_E[2][H * B];        // exp(y_t - shift), double buffered by t&1
__device__ float g_part[2][NBLK * B];  // per-block row maxes of y_t
__device__ unsigned g_flag[NBLK];      // block published step t => flag == t+1

__device__ __forceinline__ ull splat2(float v) {
    ull r; asm("mov.b64 %0, {%1, %1};" : "=l"(r) : "f"(v)); return r;
}
__device__ __forceinline__ ull fma2(ull a, ull b, ull c) {
    ull d; asm("fma.rn.f32x2 %0, %1, %2, %3;" : "=l"(d) : "l"(a), "l"(b), "l"(c)); return d;
}
__device__ __forceinline__ ull add2(ull a, ull b) {
    ull d; asm("add.rn.f32x2 %0, %1, %2;" : "=l"(d) : "l"(a), "l"(b)); return d;
}
__device__ __forceinline__ void upk(ull v, float& lo, float& hi) {
    asm("mov.b64 {%0, %1}, %2;" : "=f"(lo), "=f"(hi) : "l"(v));
}
__device__ __forceinline__ ull shflx16(ull v) {
    unsigned lo = (unsigned)v, hi = (unsigned)(v >> 32);
    lo = __shfl_xor_sync(0xffffffffu, lo, 16);
    hi = __shfl_xor_sync(0xffffffffu, hi, 16);
    return ((ull)hi << 32) | lo;
}

// ---------------------------------------------------------------------------
__global__ void init_flags_kernel() {
    if (threadIdx.x < NBLK) g_flag[threadIdx.x] = 0u;
}

// ---------------------------------------------------------------------------
__global__ void gamma_kernel(const float* __restrict__ gamma) {
    __shared__ float red[256];
    __shared__ float s_max, s_sum;
    int tid = threadIdx.x;
    float mx = -3.4e38f;
    for (int i = tid; i < H; i += 256) mx = fmaxf(mx, gamma[i]);
    red[tid] = mx;
    __syncthreads();
    for (int o = 128; o > 0; o >>= 1) {
        if (tid < o) red[tid] = fmaxf(red[tid], red[tid + o]);
        __syncthreads();
    }
    if (tid == 0) s_max = red[0];
    __syncthreads();
    float m = s_max;
    float sm = 0.f;
    for (int i = tid; i < H; i += 256) sm += __expf(gamma[i] - m);
    __syncthreads();
    red[tid] = sm;
    __syncthreads();
    for (int o = 128; o > 0; o >>= 1) {
        if (tid < o) red[tid] += red[tid + o];
        __syncthreads();
    }
    if (tid == 0) s_sum = red[0];
    __syncthreads();
    float inv = 1.0f / s_sum;
    for (int i = tid; i < H; i += 256) g_gamma_exp[i] = __expf(gamma[i] - m) * inv;
}

// ---------------------------------------------------------------------------
// persistent kernel: t=0 init + 255 recurrence steps, flat flag barriers
// ---------------------------------------------------------------------------
__global__ void __launch_bounds__(NTHR, 1) hmm_persist(
    const int* __restrict__ ids, const float* __restrict__ alpha,
    const float* __restrict__ beta, float* __restrict__ out) {
    extern __shared__ float smem[];
    float* s_a = smem;                 // [2048][16]  alpha slice, [k][r] (131072B)
    float* s_part = s_a + H * 16;      // [256][16]   k-slice partials (16KB)
    float* s_y = s_part + 256 * 16;    // [256]
    float* s_m = s_y + 256;            // [16]  current shift for E publish
    float* s_old = s_m + 16;           // [16]  shift used in E_{t-1}
    float* s_red = s_old + 16;         // [16][16]

    const int tid = threadIdx.x;
    const int blk = blockIdx.x;
    const int r0 = blk * 16;
    const int lane = tid & 31, w = tid >> 5;
    const int bg = lane & 3;           // 4 b's: bg*4..bg*4+3
    const int rg = (lane >> 2) & 3;    // 4 rows: rg*4..rg*4+3
    const int khalf = lane >> 4;       // k parity within warp's 128-k range
    const int orow = tid >> 4, ob = tid & 15;  // epilogue mapping (tid<256)

    // stage alpha slice transposed: s_a[k*16 + rl] = alpha[(r0+rl)*H + k]
    for (int rl = 0; rl < 16; rl++) {
        const float* ap = alpha + (size_t)(r0 + rl) * H;
        for (int k = tid; k < H; k += NTHR) s_a[k * 16 + rl] = __ldg(ap + k);
    }
    if (tid < 16) s_m[tid] = 0.f;
    __syncthreads();

    // ---- t = 0: y0 = masked beta gather; E_0 uses shift 0 (y0 <= 0)
    {
        if (tid < 256) {
            int id = __ldg(&ids[ob * S + (S - 1)]);
            float bv = __ldg(&beta[(size_t)(r0 + orow) * V + (id < 0 ? 0 : id)]);
            float y0 = (id < 0) ? 0.f : bv;
            out[(size_t)(r0 + orow) * B + ob] = y0;
            s_y[tid] = y0;
            g_E[0][(r0 + orow) * B + ob] = __expf(y0);
        }
        __syncthreads();
        if (tid < 16) {
            float mx = s_y[tid];
            #pragma unroll
            for (int rr = 1; rr < 16; rr++) mx = fmaxf(mx, s_y[rr * 16 + tid]);
            g_part[0][blk * B + tid] = mx;
        }
        __threadfence();
        __syncthreads();
        if (tid == 0) atomicExch(&g_flag[blk], 1u);
    }

    // ---- main recurrence
    for (int t = 1; t < S; t++) {
        const int par = (t - 1) & 1;

        // prefetch ip (independent of barrier)
        float ipv = 0.f;
        if (tid < 256) {
            int id = __ldg(&ids[ob * S + (S - 1 - t)]);
            float bv = __ldg(&beta[(size_t)(r0 + orow) * V + (id < 0 ? 0 : id)]);
            ipv = (id < 0) ? 0.f : bv;
        }

        // flat barrier: all blocks published step t-1
        if (tid < NBLK) {
            volatile unsigned* f = &g_flag[tid];
            while (*f < (unsigned)t) {}
        }
        __syncthreads();

        // s_old <- shift used in E_{t-1};  s_m <- m_{t-1} (for publishing E_t)
        if (tid < 16) s_old[tid] = s_m[tid];
        __syncthreads();
        if (tid < 256) {
            int g = tid >> 4;
            const float* gp = g_part[par];
            float mx = -3.4e38f;
            #pragma unroll
            for (int j = 0; j < 8; j++) mx = fmaxf(mx, __ldcg(gp + (g * 8 + j) * B + ob));
            s_red[g * 16 + ob] = mx;
        }
        __syncthreads();
        if (tid < 16) {
            float mx = s_red[tid];
            #pragma unroll
            for (int g = 1; g < 16; g++) mx = fmaxf(mx, s_red[g * 16 + tid]);
            s_m[tid] = mx;
        }

        // ---- dot: acc[rl][bp] over this thread's 64 k values
        const float* Eg = g_E[par];
        ull acc[4][2];
        #pragma unroll
        for (int l = 0; l < 4; l++) { acc[l][0] = 0ull; acc[l][1] = 0ull; }

        const int kbase = w * 128 + khalf;
        #pragma unroll 8
        for (int i = 0; i < 64; i++) {
            const int k = kbase + 2 * i;
            ulonglong2 ev = __ldcg(reinterpret_cast<const ulonglong2*>(Eg + k * 16 + bg * 4));
            float4 av = *reinterpret_cast<const float4*>(s_a + k * 16 + rg * 4);
            ull a0 = splat2(av.x), a1 = splat2(av.y), a2 = splat2(av.z), a3 = splat2(av.w);
            acc[0][0] = fma2(a0, ev.x, acc[0][0]);
            acc[0][1] = fma2(a0, ev.y, acc[0][1]);
            acc[1][0] = fma2(a1, ev.x, acc[1][0]);
            acc[1][1] = fma2(a1, ev.y, acc[1][1]);
            acc[2][0] = fma2(a2, ev.x, acc[2][0]);
            acc[2][1] = fma2(a2, ev.y, acc[2][1]);
            acc[3][0] = fma2(a3, ev.x, acc[3][0]);
            acc[3][1] = fma2(a3, ev.y, acc[3][1]);
        }

        // combine khalf halves within warp
        #pragma unroll
        for (int l = 0; l < 4; l++) {
            acc[l][0] = add2(acc[l][0], shflx16(acc[l][0]));
            acc[l][1] = add2(acc[l][1], shflx16(acc[l][1]));
        }
        if (khalf == 0) {
            #pragma unroll
            for (int l = 0; l < 4; l++) {
                float f0, f1;
                upk(acc[l][0], f0, f1);
                s_part[((rg * 4 + l) * 16 + bg * 4 + 0) * 16 + w] = f0;
                s_part[((rg * 4 + l) * 16 + bg * 4 + 1) * 16 + w] = f1;
                upk(acc[l][1], f0, f1);
                s_part[((rg * 4 + l) * 16 + bg * 4 + 2) * 16 + w] = f0;
                s_part[((rg * 4 + l) * 16 + bg * 4 + 3) * 16 + w] = f1;
            }
        }
        __syncthreads();

        // epilogue: reduce 16 warps, log, add shift + ip, publish
        if (tid < 256) {
            const float* pp = s_part + tid * 16;
            float sum = 0.f;
            #pragma unroll
            for (int c = 0; c < 16; c++) sum += pp[c];
            float y = __logf(sum) + s_old[ob] + ipv;
            out[(size_t)t * H * B + (size_t)(r0 + orow) * B + ob] = y;
            s_y[tid] = y;
            g_E[t & 1][(r0 + orow) * B + ob] = __expf(y - s_m[ob]);
        }
        __syncthreads();
        if (tid < 16) {
            float mx = s_y[tid];
            #pragma unroll
            for (int rr = 1; rr < 16; rr++) mx = fmaxf(mx, s_y[rr * 16 + tid]);
            g_part[t & 1][blk * B + tid] = mx;
        }
        __threadfence();
        __syncthreads();
        if (tid == 0) atomicExch(&g_flag[blk], (unsigned)(t + 1));
    }
}

// ---------------------------------------------------------------------------
// final[b] = log(gamma_exp . exp(y_last[:,b] - m_b)) + m_b
// ---------------------------------------------------------------------------
__global__ void final_kernel(float* __restrict__ out) {
    __shared__ float redm[16][16];
    __shared__ float reds[16][16];
    __shared__ float mv[16];
    int tid = threadIdx.x;
    int b = tid & 15, seg = tid >> 4;
    const float* yl = out + (size_t)(S - 1) * H * B;
    float mx = -3.4e38f;
    for (int h = seg; h < H; h += 16) mx = fmaxf(mx, yl[h * B + b]);
    redm[seg][b] = mx;
    __syncthreads();
    if (tid < 16) {
        float m2 = redm[0][tid];
        #pragma unroll
        for (int c = 1; c < 16; c++) m2 = fmaxf(m2, redm[c][tid]);
        mv[tid] = m2;
    }
    __syncthreads();
    float m = mv[b];
    float sm = 0.f;
    for (int h = seg; h < H; h += 16) sm += g_gamma_exp[h] * __expf(yl[h * B + b] - m);
    reds[seg][b] = sm;
    __syncthreads();
    if (tid < 16) {
        float tot = 0.f;
        #pragma unroll
        for (int c = 0; c < 16; c++) tot += reds[c][tid];
        out[(size_t)S * H * B + tid] = __logf(tot) + mv[tid];
    }
}

// ---------------------------------------------------------------------------
extern "C" void kernel_launch(void* const* d_in, const int* in_sizes, int n_in,
                              void* d_out, int out_size) {
    const int* ids = (const int*)d_in[0];        // (B, S) int32
    const float* alpha = (const float*)d_in[1];  // (H, H)
    const float* beta = (const float*)d_in[2];   // (H, V)
    const float* gamma = (const float*)d_in[3];  // (H,)
    float* out = (float*)d_out;                  // ys (S,H,B) then final (B,)

    const int smem_bytes = (H * 16 + 256 * 16 + 256 + 16 + 16 + 256) * (int)sizeof(float);
    cudaFuncSetAttribute(hmm_persist, cudaFuncAttributeMaxDynamicSharedMemorySize, smem_bytes);

    init_flags_kernel<<<1, 128>>>();
    gamma_kernel<<<1, 256>>>(gamma);
    hmm_persist<<<NBLK, NTHR, smem_bytes>>>(ids, alpha, beta, out);
    final_kernel<<<1, 256>>>(out);
}